// round 1
// baseline (speedup 1.0000x reference)
#include <cuda_runtime.h>

#define NB 8
#define NL 4096
#define NK 16
#define ND 128

// scratch: neighbor indices (allocation-free rule -> __device__ global)
__device__ int g_nbr[NB * NL * NK];

// ---------------------------------------------------------------------------
// Kernel 1: brute-force 16-NN per query + rotated deltas (euclidian output)
// One thread = one query point. Centers of the whole batch staged in smem as
// SoA (sx/sy/sz) so the inner scan is a broadcast LDS (conflict-free).
// ---------------------------------------------------------------------------
__global__ __launch_bounds__(256, 1)
void knn_kernel(const float* __restrict__ frame,
                float* __restrict__ eucl_out)
{
    __shared__ float sx[NL];
    __shared__ float sy[NL];
    __shared__ float sz[NL];

    const int b   = blockIdx.y;
    const int tid = threadIdx.x;
    const float* fb = frame + (size_t)b * NL * 12;   // [L][4][3]

    for (int j = tid; j < NL; j += 256) {
        const float* p = fb + j * 12;                // frame[b,j,0,:]
        sx[j] = p[0];
        sy[j] = p[1];
        sz[j] = p[2];
    }
    __syncthreads();

    const int q = blockIdx.x * 256 + tid;
    const float cx = sx[q], cy = sy[q], cz = sz[q];

    float bd[NK];
    int   bi[NK];
#pragma unroll
    for (int i = 0; i < NK; i++) { bd[i] = 3.0e38f; bi[i] = 0; }

#pragma unroll 4
    for (int j = 0; j < NL; j++) {
        // exact, unfused arithmetic to match XLA's diff*diff -> sum
        float dx = __fadd_rn(sx[j], -cx);
        float dy = __fadd_rn(sy[j], -cy);
        float dz = __fadd_rn(sz[j], -cz);
        float d  = __fadd_rn(__fadd_rn(__fmul_rn(dx, dx), __fmul_rn(dy, dy)),
                             __fmul_rn(dz, dz));
        if (d < bd[NK - 1]) {
            // stable register insertion sort (strict < => lower index wins ties,
            // matching jax.lax.top_k)
            float cd = d;
            int   ci = j;
#pragma unroll
            for (int i = 0; i < NK; i++) {
                if (cd < bd[i]) {
                    float td = bd[i]; bd[i] = cd; cd = td;
                    int   ti = bi[i]; bi[i] = ci; ci = ti;
                }
            }
        }
    }

    // rotation rows: frame[b,q,1:4,:]  (R[c][r] = frame[b,q,1+c,r])
    float R[3][3];
    const float* fr = fb + q * 12 + 3;
#pragma unroll
    for (int c = 0; c < 3; c++)
#pragma unroll
        for (int r = 0; r < 3; r++)
            R[c][r] = fr[c * 3 + r];

    const size_t base = ((size_t)b * NL + q) * NK;
    float* eo = eucl_out + base * 3;
#pragma unroll
    for (int k = 0; k < NK; k++) {
        const int n = bi[k];
        g_nbr[base + k] = n;
        float d0 = sx[n] - cx;
        float d1 = sy[n] - cy;
        float d2 = sz[n] - cz;
        eo[k * 3 + 0] = d0 * R[0][0] + d1 * R[1][0] + d2 * R[2][0];
        eo[k * 3 + 1] = d0 * R[0][1] + d1 * R[1][1] + d2 * R[2][1];
        eo[k * 3 + 2] = d0 * R[0][2] + d1 * R[1][2] + d2 * R[2][2];
    }
}

// ---------------------------------------------------------------------------
// Kernel 2: attribute gather. One warp per output row (128 floats = 32 x
// float4), fully coalesced stores; reads are L2-resident (attr = 16 MB).
// ---------------------------------------------------------------------------
__global__ __launch_bounds__(256, 8)
void gather_kernel(const float* __restrict__ attr,
                   float* __restrict__ gout)
{
    const int warp = (blockIdx.x * 256 + threadIdx.x) >> 5;
    const int lane = threadIdx.x & 31;
    // warp in [0, NB*NL*NK)
    const int b   = warp / (NL * NK);
    const int n   = g_nbr[warp];

    const float4* src = (const float4*)(attr + ((size_t)b * NL + n) * ND);
    float4*       dst = (float4*)(gout + (size_t)warp * ND);
    dst[lane] = src[lane];
}

extern "C" void kernel_launch(void* const* d_in, const int* in_sizes, int n_in,
                              void* d_out, int out_size)
{
    // metadata order: frame [B,L,4,3] then attr [B,L,D]; swap defensively
    const float* frame = (const float*)d_in[0];
    const float* attr  = (const float*)d_in[1];
    if (in_sizes[0] != NB * NL * 12) {
        frame = (const float*)d_in[1];
        attr  = (const float*)d_in[0];
    }

    float* eucl = (float*)d_out;                         // B*L*K*3 floats
    float* gath = (float*)d_out + (size_t)NB * NL * NK * 3;

    dim3 grid1(NL / 256, NB);
    knn_kernel<<<grid1, 256>>>(frame, eucl);

    const int rows = NB * NL * NK;           // 524288 rows, 8 warps/block
    gather_kernel<<<rows / 8, 256>>>(attr, gath);
}

// round 2
// speedup vs baseline: 1.0496x; 1.0496x over previous
#include <cuda_runtime.h>

#define NB 8
#define NL 4096
#define NK 16
#define ND 128

#define QPB 128          // queries per block
#define TPB 256          // threads per block (2 threads per query)
#define TILE 1024        // candidates staged per smem tile
#define NTILES (NL / TILE)

// scratch: neighbor indices (allocation-free rule -> __device__ global)
__device__ int g_nbr[NB * NL * NK];

// ---------------------------------------------------------------------------
// sorted-ascending top-16 insert, split at the median to shorten the
// predicated swap chain (avg ~8 steps instead of 16). Strict '<' everywhere
// => stable (lower index wins ties), matching jax.lax.top_k.
// ---------------------------------------------------------------------------
__device__ __forceinline__ void ins16(float (&bd)[NK], int (&bi)[NK],
                                      float d, int j)
{
    if (d < bd[7]) {
        // evictee of lower half goes to slot 8; upper half shifts down
#pragma unroll
        for (int i = 15; i > 8; --i) { bd[i] = bd[i - 1]; bi[i] = bi[i - 1]; }
        bd[8] = bd[7]; bi[8] = bi[7];
        float cd = d; int ci = j;
#pragma unroll
        for (int i = 0; i < 8; ++i) {
            if (cd < bd[i]) {
                float td = bd[i]; bd[i] = cd; cd = td;
                int   ti = bi[i]; bi[i] = ci; ci = ti;
            }
        }
    } else {
        float cd = d; int ci = j;
#pragma unroll
        for (int i = 8; i < 16; ++i) {
            if (cd < bd[i]) {
                float td = bd[i]; bd[i] = cd; cd = td;
                int   ti = bi[i]; bi[i] = ci; ci = ti;
            }
        }
    }
}

__device__ __forceinline__ unsigned long long pack2(float lo, float hi)
{
    unsigned long long r;
    asm("mov.b64 %0, {%1, %2};" : "=l"(r) : "f"(lo), "f"(hi));
    return r;
}

// ---------------------------------------------------------------------------
// Kernel 1: brute-force 16-NN, 2 threads per query (split-K over candidates),
// packed f32x2 distance math, tiled smem staging, exact merge.
// ---------------------------------------------------------------------------
__global__ __launch_bounds__(TPB, 3)
void knn_kernel(const float* __restrict__ frame,
                float* __restrict__ eucl_out)
{
    __shared__ __align__(16) unsigned char smem_raw[32768];
    float* sx = (float*)smem_raw;            // TILE floats
    float* sy = sx + TILE;
    float* sz = sy + TILE;

    const int tid = threadIdx.x;
    const int h   = tid & 1;                 // which half of candidate space
    const int q   = blockIdx.x * QPB + (tid >> 1);   // global query id
    const int b   = q / NL;
    const int ql  = q - b * NL;
    const float* fb = frame + (size_t)b * NL * 12;   // [L][4][3]
    const float* fq = fb + ql * 12;

    const float cx = fq[0], cy = fq[1], cz = fq[2];
    const unsigned long long ncx2 = pack2(-cx, -cx);
    const unsigned long long ncy2 = pack2(-cy, -cy);
    const unsigned long long ncz2 = pack2(-cz, -cz);

    float bd[NK];
    int   bi[NK];
#pragma unroll
    for (int i = 0; i < NK; i++) { bd[i] = 3.0e38f; bi[i] = 0; }

    const unsigned long long* px = (const unsigned long long*)sx;
    const unsigned long long* py = (const unsigned long long*)sy;
    const unsigned long long* pz = (const unsigned long long*)sz;

    for (int t = 0; t < NTILES; ++t) {
        const int tb = t * TILE;
        __syncthreads();
        for (int i = tid; i < TILE; i += TPB) {
            const float* p = fb + (size_t)(tb + i) * 12;   // frame[b,j,0,:]
            sx[i] = p[0];
            sy[i] = p[1];
            sz[i] = p[2];
        }
        __syncthreads();

        // thread handles pairs pp with pp%2 == h  (candidates 2pp, 2pp+1)
#pragma unroll 4
        for (int pp = h; pp < TILE / 2; pp += 2) {
            unsigned long long x2 = px[pp], y2 = py[pp], z2 = pz[pp];
            unsigned long long dx2, dy2, dz2, m0, m1, m2, s0, dd;
            // exact unfused arithmetic (identical IEEE rn per lane)
            asm("add.rn.f32x2 %0, %1, %2;" : "=l"(dx2) : "l"(x2), "l"(ncx2));
            asm("add.rn.f32x2 %0, %1, %2;" : "=l"(dy2) : "l"(y2), "l"(ncy2));
            asm("add.rn.f32x2 %0, %1, %2;" : "=l"(dz2) : "l"(z2), "l"(ncz2));
            asm("mul.rn.f32x2 %0, %1, %2;" : "=l"(m0) : "l"(dx2), "l"(dx2));
            asm("mul.rn.f32x2 %0, %1, %2;" : "=l"(m1) : "l"(dy2), "l"(dy2));
            asm("mul.rn.f32x2 %0, %1, %2;" : "=l"(m2) : "l"(dz2), "l"(dz2));
            asm("add.rn.f32x2 %0, %1, %2;" : "=l"(s0) : "l"(m0), "l"(m1));
            asm("add.rn.f32x2 %0, %1, %2;" : "=l"(dd) : "l"(s0), "l"(m2));
            float d0, d1;
            asm("mov.b64 {%0, %1}, %2;" : "=f"(d0), "=f"(d1) : "l"(dd));

            if (fminf(d0, d1) < bd[15]) {
                const int j0 = tb + 2 * pp;
                if (d0 < bd[15]) ins16(bd, bi, d0, j0);
                if (d1 < bd[15]) ins16(bd, bi, d1, j0 + 1);
            }
        }
    }

    // -------- merge the two half-lists per query (exact, stable) ----------
    __syncthreads();                          // done reading tile smem
    float* md = (float*)smem_raw;             // 256*16 floats
    int*   mi = (int*)(smem_raw + TPB * NK * 4);
#pragma unroll
    for (int k = 0; k < NK; ++k) { md[tid * NK + k] = bd[k]; mi[tid * NK + k] = bi[k]; }
    __syncthreads();

    if (h == 0) {
        const int pa = tid * NK, pb = pa + NK;
        int ia = 0, ib = 0;
        float fd_[NK]; int fi_[NK];
#pragma unroll
        for (int k = 0; k < NK; ++k) {
            float da = md[pa + ia], db = md[pb + ib];
            int   ja = mi[pa + ia], jb = mi[pb + ib];
            bool ta = (da < db) || (da == db && ja < jb);   // lexicographic (d, idx)
            fd_[k] = ta ? da : db;
            fi_[k] = ta ? ja : jb;
            if (ta) ia++; else ib++;
        }
        (void)fd_;

        // rotation rows: frame[b,q,1:4,:]  (R[c][r] = fq[3 + c*3 + r])
        float R[3][3];
#pragma unroll
        for (int c = 0; c < 3; c++)
#pragma unroll
            for (int r = 0; r < 3; r++)
                R[c][r] = fq[3 + c * 3 + r];

        const size_t base = (size_t)q * NK;
        float* eo = eucl_out + base * 3;
#pragma unroll
        for (int k = 0; k < NK; ++k) {
            const int n = fi_[k];
            g_nbr[base + k] = n;
            const float* fn = fb + (size_t)n * 12;
            float d0 = fn[0] - cx;
            float d1 = fn[1] - cy;
            float d2 = fn[2] - cz;
            eo[k * 3 + 0] = d0 * R[0][0] + d1 * R[1][0] + d2 * R[2][0];
            eo[k * 3 + 1] = d0 * R[0][1] + d1 * R[1][1] + d2 * R[2][1];
            eo[k * 3 + 2] = d0 * R[0][2] + d1 * R[1][2] + d2 * R[2][2];
        }
    }
}

// ---------------------------------------------------------------------------
// Kernel 2: attribute gather. 4 rows per warp (8 lanes per row, 4 float4 per
// lane) -> 4 LDG.128 + 4 STG.128 in flight per lane for MLP.
// ---------------------------------------------------------------------------
__global__ __launch_bounds__(256, 8)
void gather_kernel(const float* __restrict__ attr,
                   float* __restrict__ gout)
{
    const int warp = (blockIdx.x * 256 + threadIdx.x) >> 5;
    const int lane = threadIdx.x & 31;
    const int row  = warp * 4 + (lane >> 3);      // 4 rows per warp
    const int l8   = lane & 7;

    const int b = row / (NL * NK);
    const int n = g_nbr[row];

    const float4* src = (const float4*)(attr + ((size_t)b * NL + n) * ND);
    float4*       dst = (float4*)(gout + (size_t)row * ND);

    float4 v0 = src[l8];
    float4 v1 = src[l8 + 8];
    float4 v2 = src[l8 + 16];
    float4 v3 = src[l8 + 24];
    dst[l8]      = v0;
    dst[l8 + 8]  = v1;
    dst[l8 + 16] = v2;
    dst[l8 + 24] = v3;
}

extern "C" void kernel_launch(void* const* d_in, const int* in_sizes, int n_in,
                              void* d_out, int out_size)
{
    const float* frame = (const float*)d_in[0];
    const float* attr  = (const float*)d_in[1];
    if (in_sizes[0] != NB * NL * 12) {
        frame = (const float*)d_in[1];
        attr  = (const float*)d_in[0];
    }

    float* eucl = (float*)d_out;                          // B*L*K*3 floats
    float* gath = (float*)d_out + (size_t)NB * NL * NK * 3;

    const int nq = NB * NL;
    knn_kernel<<<nq / QPB, TPB>>>(frame, eucl);

    const int rows = NB * NL * NK;                        // 524288
    gather_kernel<<<rows / 32, 256>>>(attr, gath);        // 4 rows/warp, 8 warps/blk
}

// round 3
// speedup vs baseline: 1.8773x; 1.7887x over previous
#include <cuda_runtime.h>

#define NB 8
#define NL 4096
#define NK 16
#define ND 128

#define QPB 128          // queries per block
#define TPB 256          // threads per block (2 threads per query)
#define TILE 1024        // candidates staged per smem tile
#define NTILES (NL / TILE)
#define BCAP 16          // per-thread candidate buffer capacity

// scratch: neighbor indices (allocation-free rule -> __device__ global)
__device__ int g_nbr[NB * NL * NK];

// ---------------------------------------------------------------------------
// sorted-ascending top-16 insert, split at the median. Strict '<' everywhere
// => stable (lower index wins ties), matching jax.lax.top_k.
// ---------------------------------------------------------------------------
__device__ __forceinline__ void ins16(float (&bd)[NK], int (&bi)[NK],
                                      float d, int j)
{
    if (d < bd[7]) {
#pragma unroll
        for (int i = 15; i > 8; --i) { bd[i] = bd[i - 1]; bi[i] = bi[i - 1]; }
        bd[8] = bd[7]; bi[8] = bi[7];
        float cd = d; int ci = j;
#pragma unroll
        for (int i = 0; i < 8; ++i) {
            if (cd < bd[i]) {
                float td = bd[i]; bd[i] = cd; cd = td;
                int   ti = bi[i]; bi[i] = ci; ci = ti;
            }
        }
    } else {
        float cd = d; int ci = j;
#pragma unroll
        for (int i = 8; i < 16; ++i) {
            if (cd < bd[i]) {
                float td = bd[i]; bd[i] = cd; cd = td;
                int   ti = bi[i]; bi[i] = ci; ci = ti;
            }
        }
    }
}

__device__ __forceinline__ unsigned long long pack2(float lo, float hi)
{
    unsigned long long r;
    asm("mov.b64 %0, {%1, %2};" : "=l"(r) : "f"(lo), "f"(hi));
    return r;
}

// ---------------------------------------------------------------------------
// Kernel 1: brute-force 16-NN, 2 threads per query (split-K), packed f32x2
// distance math, predicated candidate buffering + warp-synchronized flushes.
// ---------------------------------------------------------------------------
__global__ __launch_bounds__(TPB, 3)
void knn_kernel(const float* __restrict__ frame,
                float* __restrict__ eucl_out)
{
    __shared__ __align__(16) unsigned char smem_raw[32768];
    float* sx = (float*)smem_raw;            // TILE floats
    float* sy = sx + TILE;
    float* sz = sy + TILE;

    const int tid = threadIdx.x;
    const int h   = tid & 1;                 // which half of candidate space
    const int q   = blockIdx.x * QPB + (tid >> 1);   // global query id
    const int b   = q / NL;
    const int ql  = q - b * NL;
    const float* fb = frame + (size_t)b * NL * 12;   // [L][4][3]
    const float* fq = fb + ql * 12;

    const float cx = fq[0], cy = fq[1], cz = fq[2];
    const unsigned long long ncx2 = pack2(-cx, -cx);
    const unsigned long long ncy2 = pack2(-cy, -cy);
    const unsigned long long ncz2 = pack2(-cz, -cz);

    float bd[NK];
    int   bi[NK];
#pragma unroll
    for (int i = 0; i < NK; i++) { bd[i] = 3.0e38f; bi[i] = 0; }

    float2 lbuf[BCAP];                       // local-mem candidate buffer
    int    cnt = 0;
    float  tau = 3.0e38f;                    // stale copy of bd[15] (only shrinks)

    const unsigned long long* px = (const unsigned long long*)sx;
    const unsigned long long* py = (const unsigned long long*)sy;
    const unsigned long long* pz = (const unsigned long long*)sz;

    for (int t = 0; t < NTILES; ++t) {
        const int tb = t * TILE;
        __syncthreads();
        for (int i = tid; i < TILE; i += TPB) {
            const float* p = fb + (size_t)(tb + i) * 12;   // frame[b,j,0,:]
            sx[i] = p[0];
            sy[i] = p[1];
            sz[i] = p[2];
        }
        __syncthreads();

        // thread handles pairs pp with pp%2 == h  (candidates 2pp, 2pp+1)
#pragma unroll 4
        for (int pp = h; pp < TILE / 2; pp += 2) {
            unsigned long long x2 = px[pp], y2 = py[pp], z2 = pz[pp];
            unsigned long long dx2, dy2, dz2, m0, m1, m2, s0, dd;
            // exact unfused arithmetic (identical IEEE rn per lane)
            asm("add.rn.f32x2 %0, %1, %2;" : "=l"(dx2) : "l"(x2), "l"(ncx2));
            asm("add.rn.f32x2 %0, %1, %2;" : "=l"(dy2) : "l"(y2), "l"(ncy2));
            asm("add.rn.f32x2 %0, %1, %2;" : "=l"(dz2) : "l"(z2), "l"(ncz2));
            asm("mul.rn.f32x2 %0, %1, %2;" : "=l"(m0) : "l"(dx2), "l"(dx2));
            asm("mul.rn.f32x2 %0, %1, %2;" : "=l"(m1) : "l"(dy2), "l"(dy2));
            asm("mul.rn.f32x2 %0, %1, %2;" : "=l"(m2) : "l"(dz2), "l"(dz2));
            asm("add.rn.f32x2 %0, %1, %2;" : "=l"(s0) : "l"(m0), "l"(m1));
            asm("add.rn.f32x2 %0, %1, %2;" : "=l"(dd) : "l"(s0), "l"(m2));
            float d0, d1;
            asm("mov.b64 {%0, %1}, %2;" : "=f"(d0), "=f"(d1) : "l"(dd));

            const int j0 = tb + 2 * pp;
            // branch-free predicated pushes (@P STL.64 + @P IADD)
            if (d0 < tau) { lbuf[cnt] = make_float2(d0, __int_as_float(j0));     cnt++; }
            if (d1 < tau) { lbuf[cnt] = make_float2(d1, __int_as_float(j0 + 1)); cnt++; }

            // warp-synchronized flush: all lanes' inserts coalesce here
            if (__any_sync(0xffffffffu, cnt >= BCAP - 2)) {
                for (int i = 0; i < cnt; ++i) {
                    float d = lbuf[i].x;
                    if (d < bd[NK - 1])
                        ins16(bd, bi, d, __float_as_int(lbuf[i].y));
                }
                cnt = 0;
                tau = bd[NK - 1];
            }
        }
    }

    // final flush
    for (int i = 0; i < cnt; ++i) {
        float d = lbuf[i].x;
        if (d < bd[NK - 1])
            ins16(bd, bi, d, __float_as_int(lbuf[i].y));
    }

    // -------- merge the two half-lists per query (exact, stable) ----------
    __syncthreads();                          // done reading tile smem
    float* md = (float*)smem_raw;             // 256*16 floats
    int*   mi = (int*)(smem_raw + TPB * NK * 4);
#pragma unroll
    for (int k = 0; k < NK; ++k) { md[tid * NK + k] = bd[k]; mi[tid * NK + k] = bi[k]; }
    __syncthreads();

    if (h == 0) {
        const int pa = tid * NK, pb = pa + NK;
        int ia = 0, ib = 0;
        int fi_[NK];
#pragma unroll
        for (int k = 0; k < NK; ++k) {
            float da = md[pa + ia], db = md[pb + ib];
            int   ja = mi[pa + ia], jb = mi[pb + ib];
            bool ta = (da < db) || (da == db && ja < jb);   // lexicographic (d, idx)
            fi_[k] = ta ? ja : jb;
            if (ta) ia++; else ib++;
        }

        // rotation rows: frame[b,q,1:4,:]  (R[c][r] = fq[3 + c*3 + r])
        float R[3][3];
#pragma unroll
        for (int c = 0; c < 3; c++)
#pragma unroll
            for (int r = 0; r < 3; r++)
                R[c][r] = fq[3 + c * 3 + r];

        const size_t base = (size_t)q * NK;
        float* eo = eucl_out + base * 3;
#pragma unroll
        for (int k = 0; k < NK; ++k) {
            const int n = fi_[k];
            g_nbr[base + k] = n;
            const float* fn = fb + (size_t)n * 12;
            float d0 = fn[0] - cx;
            float d1 = fn[1] - cy;
            float d2 = fn[2] - cz;
            eo[k * 3 + 0] = d0 * R[0][0] + d1 * R[1][0] + d2 * R[2][0];
            eo[k * 3 + 1] = d0 * R[0][1] + d1 * R[1][1] + d2 * R[2][1];
            eo[k * 3 + 2] = d0 * R[0][2] + d1 * R[1][2] + d2 * R[2][2];
        }
    }
}

// ---------------------------------------------------------------------------
// Kernel 2: attribute gather. 8 rows per warp (4 lanes per row, 8 float4 per
// lane) -> 8 LDG.128 + 8 STG.128 in flight per lane.
// ---------------------------------------------------------------------------
__global__ __launch_bounds__(256, 8)
void gather_kernel(const float* __restrict__ attr,
                   float* __restrict__ gout)
{
    const int warp = (blockIdx.x * 256 + threadIdx.x) >> 5;
    const int lane = threadIdx.x & 31;
    const int row  = warp * 8 + (lane >> 2);      // 8 rows per warp
    const int l4   = lane & 3;

    const int b = row / (NL * NK);
    const int n = g_nbr[row];

    const float4* src = (const float4*)(attr + ((size_t)b * NL + n) * ND);
    float4*       dst = (float4*)(gout + (size_t)row * ND);

    float4 v[8];
#pragma unroll
    for (int i = 0; i < 8; ++i) v[i] = src[i * 4 + l4];
#pragma unroll
    for (int i = 0; i < 8; ++i) dst[i * 4 + l4] = v[i];
}

extern "C" void kernel_launch(void* const* d_in, const int* in_sizes, int n_in,
                              void* d_out, int out_size)
{
    const float* frame = (const float*)d_in[0];
    const float* attr  = (const float*)d_in[1];
    if (in_sizes[0] != NB * NL * 12) {
        frame = (const float*)d_in[1];
        attr  = (const float*)d_in[0];
    }

    float* eucl = (float*)d_out;                          // B*L*K*3 floats
    float* gath = (float*)d_out + (size_t)NB * NL * NK * 3;

    const int nq = NB * NL;
    knn_kernel<<<nq / QPB, TPB>>>(frame, eucl);

    const int rows = NB * NL * NK;                        // 524288
    gather_kernel<<<rows / 64, 256>>>(attr, gath);        // 8 rows/warp, 8 warps/blk
}